// round 13
// baseline (speedup 1.0000x reference)
#include <cuda_runtime.h>
#include <cuda_bf16.h>
#include <cstdint>

// ---------------------------------------------------------------------------
// SDNE graph autoencoder: 4x GraphConv (PyG) + leaky_relu(0.01).
//   layer: out = segsum(h[src]->dst) @ Wrel^T + b + h @ Wroot^T
// Linearity: aggregate in min(d_in, d_out) dim.
// Aggregation: CSR (zero, decode+detect+hist, single-block scan, fill)
//   + warp-per-node gather; epilogues emit bf16 hi/lo splits.
// GEMM: mma.sync m16n8k16 bf16 hi/lo split (D += Ah*Bh + Ah*Bl + Al*Bh),
//   128x64 CTA tile, 2-stage cp.async, one launch per layer.
// ---------------------------------------------------------------------------

#define NMAX  50000
#define EMAX  1000000
#define LEAKY 0.01f
typedef __nv_bfloat16 bf16;

// ------------------------------- scratch -----------------------------------
__device__ __align__(16) float g_t   [(size_t)NMAX * 128];
__device__ __align__(16) float g_s   [(size_t)NMAX * 128];
__device__ __align__(16) float g_emb [(size_t)NMAX * 64];
__device__ __align__(16) bf16  g_bufh[(size_t)NMAX * 256];
__device__ __align__(16) bf16  g_bufl[(size_t)NMAX * 256];
__device__ __align__(16) bf16  g_aggh[(size_t)NMAX * 128];
__device__ __align__(16) bf16  g_aggl[(size_t)NMAX * 128];
__device__ __align__(16) bf16  g_xh  [(size_t)NMAX * 128];
__device__ __align__(16) bf16  g_xl  [(size_t)NMAX * 128];
__device__ __align__(16) bf16  g_embh[(size_t)NMAX * 64];
__device__ __align__(16) bf16  g_embl[(size_t)NMAX * 64];
__device__ __align__(16) bf16  g_wh  [262144];
__device__ __align__(16) bf16  g_wl  [262144];
__device__ int g_rowptr[NMAX + 1];
__device__ int g_cnt   [2 * NMAX];
__device__ __align__(16) int g_csr   [EMAX];
__device__ __align__(16) int g_src   [EMAX];
__device__ __align__(16) int g_dst   [EMAX];

// --------------------------- helpers ----------------------------------------
__device__ __forceinline__ uint32_t smem_to_u32(const void* p) {
    uint32_t a;
    asm("{ .reg .u64 t; cvta.to.shared.u64 t, %1; cvt.u32.u64 %0, t; }"
        : "=r"(a) : "l"(p));
    return a;
}

#define LDSM4(r, addr) \
    asm volatile("ldmatrix.sync.aligned.m8n8.x4.shared.b16 {%0,%1,%2,%3}, [%4];" \
        : "=r"((r)[0]), "=r"((r)[1]), "=r"((r)[2]), "=r"((r)[3]) : "r"(addr))

#define MMA_BF16(c, a, b0r, b1r) \
    asm volatile("mma.sync.aligned.m16n8k16.row.col.f32.bf16.bf16.f32 " \
        "{%0,%1,%2,%3}, {%4,%5,%6,%7}, {%8,%9}, {%0,%1,%2,%3};" \
        : "+f"((c)[0]), "+f"((c)[1]), "+f"((c)[2]), "+f"((c)[3]) \
        : "r"((a)[0]), "r"((a)[1]), "r"((a)[2]), "r"((a)[3]), \
          "r"(b0r), "r"(b1r))

#define CP16(dst, src, sz) \
    asm volatile("cp.async.cg.shared.global [%0], [%1], 16, %2;" \
        :: "r"(dst), "l"(src), "r"(sz) : "memory")
#define CP_COMMIT() asm volatile("cp.async.commit_group;" ::: "memory")
#define CP_WAIT0()  asm volatile("cp.async.wait_group 0;" ::: "memory")
#define CP_WAIT1()  asm volatile("cp.async.wait_group 1;" ::: "memory")

__device__ __forceinline__ void split2(float v0, float v1,
                                       uint32_t& h, uint32_t& l) {
    bf16 h0 = __float2bfloat16(v0), h1 = __float2bfloat16(v1);
    float r0 = v0 - __bfloat162float(h0);
    float r1 = v1 - __bfloat162float(h1);
    __nv_bfloat162 hh = __halves2bfloat162(h0, h1);
    __nv_bfloat162 ll = __halves2bfloat162(__float2bfloat16(r0),
                                           __float2bfloat16(r1));
    h = *(uint32_t*)&hh;
    l = *(uint32_t*)&ll;
}
__device__ __forceinline__ void split8(float4 a, float4 b, uint4& h, uint4& l) {
    split2(a.x, a.y, h.x, l.x);
    split2(a.z, a.w, h.y, l.y);
    split2(b.x, b.y, h.z, l.z);
    split2(b.z, b.w, h.w, l.w);
}

// --------------------------- CSR build --------------------------------------
// counters zeroed in a SEPARATE kernel: the zero-vs-atomic ordering across
// blocks is a real dependency (fusing it into the histogram kernel is a race).
__global__ void zero_cnt(int n2) {
    int i = blockIdx.x * blockDim.x + threadIdx.x;
    if (i < n2) g_cnt[i] = 0;
}

// decode 2 edges/thread to int32 + histogram of dst, with per-block
// int64-vs-int32 detection (OR of first 1024 odd words: int64 => high words
// all zero; int32 => node ids, ~surely nonzero).
__global__ void econv_hist(const unsigned int* __restrict__ ew, int E) {
    unsigned int any = 0;
    int lim = (E < 1024) ? E : 1024;
    for (int k = threadIdx.x; k < lim; k += blockDim.x)
        any |= ew[2 * k + 1];
    unsigned int anynz = __syncthreads_or(any != 0u);
    const int is64 = anynz ? 0 : 1;

    int i = blockIdx.x * blockDim.x + threadIdx.x;
    int e = 2 * i;
    if (e >= E) return;
    int s0, s1, d0, d1;
    bool two = (e + 1 < E);
    if (is64) {
        const long long* p = (const long long*)ew;
        if (two) {
            longlong2 sv = *(const longlong2*)(p + e);
            longlong2 dv = *(const longlong2*)(p + E + e);
            s0 = (int)sv.x; s1 = (int)sv.y;
            d0 = (int)dv.x; d1 = (int)dv.y;
        } else {
            s0 = (int)p[e]; d0 = (int)p[E + e];
            s1 = 0; d1 = 0;
        }
    } else {
        const int* p = (const int*)ew;
        if (two) {
            int2 sv = *(const int2*)(p + e);
            int2 dv = *(const int2*)(p + E + e);
            s0 = sv.x; s1 = sv.y; d0 = dv.x; d1 = dv.y;
        } else {
            s0 = p[e]; d0 = p[E + e];
            s1 = 0; d1 = 0;
        }
    }
    if (two) {
        *(int2*)(g_src + e) = make_int2(s0, s1);
        *(int2*)(g_dst + e) = make_int2(d0, d1);
        atomicAdd(&g_cnt[d0], 1);
        atomicAdd(&g_cnt[d1], 1);
    } else {
        g_src[e] = s0; g_dst[e] = d0;
        atomicAdd(&g_cnt[d0], 1);
    }
}

// single-block exclusive scan of g_cnt[0..n) into g_rowptr[0..n]
__global__ void scan_full(int n) {
    __shared__ int warp_sums[32];
    const int tid = threadIdx.x;
    const int per = (n + 1023) / 1024;
    const int beg = tid * per;
    const int end = (beg + per < n) ? beg + per : n;

    int local = 0;
    for (int i = beg; i < end; i++) local += g_cnt[i];

    const int lane = tid & 31, wid = tid >> 5;
    int s = local;
#pragma unroll
    for (int o = 1; o < 32; o <<= 1) {
        int t = __shfl_up_sync(0xFFFFFFFFu, s, o);
        if (lane >= o) s += t;
    }
    if (lane == 31) warp_sums[wid] = s;
    __syncthreads();
    if (wid == 0) {
        int ws = warp_sums[lane];
#pragma unroll
        for (int o = 1; o < 32; o <<= 1) {
            int t = __shfl_up_sync(0xFFFFFFFFu, ws, o);
            if (lane >= o) ws += t;
        }
        warp_sums[lane] = ws;
    }
    __syncthreads();
    int run = (wid ? warp_sums[wid - 1] : 0) + s - local;   // exclusive base
    for (int i = beg; i < end; i++) {
        run += g_cnt[i];
        g_rowptr[i + 1] = run;
    }
    if (tid == 0) g_rowptr[0] = 0;
}

// 2 edges/thread CSR fill
__global__ void fill_kernel(int E, int n) {
    int i = blockIdx.x * blockDim.x + threadIdx.x;
    int e = 2 * i;
    if (e >= E) return;
    if (e + 1 < E) {
        int2 d  = *(const int2*)(g_dst + e);
        int2 sv = *(const int2*)(g_src + e);
        int p0 = atomicAdd(&g_cnt[n + d.x], 1);
        g_csr[g_rowptr[d.x] + p0] = sv.x;
        int p1 = atomicAdd(&g_cnt[n + d.y], 1);
        g_csr[g_rowptr[d.y] + p1] = sv.y;
    } else {
        int d = g_dst[e], sv = g_src[e];
        int p = atomicAdd(&g_cnt[n + d], 1);
        g_csr[g_rowptr[d] + p] = sv;
    }
}

// ------------------------ warp-per-node aggregation --------------------------
// MODE: 0 = write bf16 hi/lo split only (GEMM A input)
//       1 = out fp32 = leaky(sum + s + b)                       (final layer)
//       2 = MODE1 + also write bf16 hi/lo split                 (emb layer)
template <int MODE>
__global__ void agg128_kernel(const float* __restrict__ feat,
                              float* __restrict__ outp,
                              bf16* __restrict__ oh, bf16* __restrict__ ol,
                              const float* __restrict__ svec,
                              const float* __restrict__ bias, int n) {
    int node = (int)((blockIdx.x * (long long)blockDim.x + threadIdx.x) >> 5);
    int lane = threadIdx.x & 31;
    if (node >= n) return;
    int beg = g_rowptr[node], end = g_rowptr[node + 1];
    const int c = lane * 4;
    float4 acc = make_float4(0.f, 0.f, 0.f, 0.f);
    int e = beg;
    for (; e + 1 < end; e += 2) {
        int s0 = g_csr[e], s1 = g_csr[e + 1];
        float4 v0 = *(const float4*)(feat + (size_t)s0 * 128 + c);
        float4 v1 = *(const float4*)(feat + (size_t)s1 * 128 + c);
        acc.x += v0.x; acc.y += v0.y; acc.z += v0.z; acc.w += v0.w;
        acc.x += v1.x; acc.y += v1.y; acc.z += v1.z; acc.w += v1.w;
    }
    if (e < end) {
        float4 v0 = *(const float4*)(feat + (size_t)g_csr[e] * 128 + c);
        acc.x += v0.x; acc.y += v0.y; acc.z += v0.z; acc.w += v0.w;
    }
    float4 r = acc;
    if (MODE >= 1) {
        float4 sv = *(const float4*)(svec + (size_t)node * 128 + c);
        float4 bv = *(const float4*)(bias + c);
        r.x = acc.x + sv.x + bv.x; r.y = acc.y + sv.y + bv.y;
        r.z = acc.z + sv.z + bv.z; r.w = acc.w + sv.w + bv.w;
        r.x = (r.x > 0.f) ? r.x : LEAKY * r.x;
        r.y = (r.y > 0.f) ? r.y : LEAKY * r.y;
        r.z = (r.z > 0.f) ? r.z : LEAKY * r.z;
        r.w = (r.w > 0.f) ? r.w : LEAKY * r.w;
        *(float4*)(outp + (size_t)node * 128 + c) = r;
    }
    if (MODE != 1) {
        uint32_t h0, l0, h1, l1;
        split2(r.x, r.y, h0, l0);
        split2(r.z, r.w, h1, l1);
        *(uint2*)(oh + (size_t)node * 128 + c) = make_uint2(h0, h1);
        *(uint2*)(ol + (size_t)node * 128 + c) = make_uint2(l0, l1);
    }
}

template <int MODE>
__global__ void agg64_kernel(const float* __restrict__ feat,
                             float* __restrict__ outp,
                             bf16* __restrict__ oh, bf16* __restrict__ ol,
                             const float* __restrict__ svec,
                             const float* __restrict__ bias, int n) {
    int node = (int)((blockIdx.x * (long long)blockDim.x + threadIdx.x) >> 5);
    int lane = threadIdx.x & 31;
    if (node >= n) return;
    int beg = g_rowptr[node], end = g_rowptr[node + 1];
    const int c = lane * 2;
    float2 a0 = make_float2(0.f, 0.f), a1 = a0;
    int e = beg;
    for (; e + 1 < end; e += 2) {
        int s0 = g_csr[e], s1 = g_csr[e + 1];
        float2 v0 = *(const float2*)(feat + (size_t)s0 * 64 + c);
        float2 v1 = *(const float2*)(feat + (size_t)s1 * 64 + c);
        a0.x += v0.x; a0.y += v0.y;
        a1.x += v1.x; a1.y += v1.y;
    }
    if (e < end) {
        float2 v0 = *(const float2*)(feat + (size_t)g_csr[e] * 64 + c);
        a0.x += v0.x; a0.y += v0.y;
    }
    float2 r = make_float2(a0.x + a1.x, a0.y + a1.y);
    if (MODE >= 1) {
        float2 sv = *(const float2*)(svec + (size_t)node * 64 + c);
        float2 bv = *(const float2*)(bias + c);
        r.x += sv.x + bv.x;
        r.y += sv.y + bv.y;
        r.x = (r.x > 0.f) ? r.x : LEAKY * r.x;
        r.y = (r.y > 0.f) ? r.y : LEAKY * r.y;
        *(float2*)(outp + (size_t)node * 64 + c) = r;
    }
    if (MODE != 1) {
        uint32_t h0, l0;
        split2(r.x, r.y, h0, l0);
        *(uint32_t*)(oh + (size_t)node * 64 + c) = h0;
        *(uint32_t*)(ol + (size_t)node * 64 + c) = l0;
    }
}

// --------------------- fused setup: weight split + x split -------------------
//  weight layout in g_wh/g_wl (bf16):
//  [0,      65536): L0 cat:   256 x 256  (cols 0-127 Wrel0, 128-255 Wroot0)
//  [65536,  98304): L1 stack: 128 x 256  (rows 0-63 Wrel1, 64-127 Wroot1)
//  [98304, 131072): L2 cat:   256 x 128  (cols 0-63 Wrel2, 64-127 Wroot2)
//  [131072,196608): L3 stack: 256 x 256  (rows 0-127 Wrel3, 128-255 Wroot3)
struct WPtrs {
    const float *rel0, *root0, *rel1, *root1, *rel2, *root2, *rel3, *root3;
};
#define WTASKS (196608 / 8)

__global__ void setup_kernel(WPtrs w, bf16* __restrict__ wh,
                             bf16* __restrict__ wl,
                             const float* __restrict__ x,
                             bf16* __restrict__ xh, bf16* __restrict__ xl,
                             long long xn8) {
    long long i = (long long)blockIdx.x * blockDim.x + threadIdx.x;
    if (i < WTASKS) {
        int base = (int)i * 8;
        const float* src;
        if (base < 65536) {
            int row = base >> 8, col = base & 255;
            src = (col < 128) ? w.rel0 + row * 128 + col
                              : w.root0 + row * 128 + (col - 128);
        } else if (base < 98304) {
            int j = base - 65536, row = j >> 8, col = j & 255;
            src = (row < 64) ? w.rel1 + row * 256 + col
                             : w.root1 + (row - 64) * 256 + col;
        } else if (base < 131072) {
            int j = base - 98304, row = j >> 7, col = j & 127;
            src = (col < 64) ? w.rel2 + row * 64 + col
                             : w.root2 + row * 64 + (col - 64);
        } else {
            int j = base - 131072, row = j >> 8, col = j & 255;
            src = (row < 128) ? w.rel3 + row * 256 + col
                              : w.root3 + (row - 128) * 256 + col;
        }
        float4 v0 = *(const float4*)src;
        float4 v1 = *(const float4*)(src + 4);
        uint4 h, l;
        split8(v0, v1, h, l);
        ((uint4*)wh)[i] = h;
        ((uint4*)wl)[i] = l;
        return;
    }
    long long j = i - WTASKS;
    if (j >= xn8) return;
    const float4* p = (const float4*)x + j * 2;
    uint4 h, l;
    split8(p[0], p[1], h, l);
    ((uint4*)xh)[j] = h;
    ((uint4*)xl)[j] = l;
}

// --------------------------- MMA GEMM ---------------------------------------
// C tile = A[M, K](bf16 pre-split) @ W[*, K](bf16 pre-split)^T
// Block: 256 thr (8 warps 4Mx2N), tile 128M x 64N, BK=64, chunk-xor swizzle,
// 2-stage cp.async pipeline (stage 48KB: A hi 16K, A lo 16K, W hi 8K, W lo 8K).
struct GArgs {
    const bf16 *a0h, *a0l, *a1h, *a1l;   // A sources (chunks >= ksplit -> a1)
    int rl0, rl1;                        // A row lengths (bf16 elems)
    int ksplit, nchunks;                 // 64-wide K chunks
    const bf16 *wh, *wl;                 // pre-split W base
    int w_rl;                            // W row length = K total
    const float* bias;                   // BIAS mode
    bf16 *oh, *ol; int orl;              // BIAS out (bf16 split)
    float *o0, *o1;                      // !BIAS out, split at column csplit
    int csplit, orl0, orl1;
    int M;
};

#define STAGE_BYTES 49152

template <bool BIAS>
__global__ void __launch_bounds__(256) mma_gemm(GArgs g) {
    extern __shared__ __align__(16) unsigned char sm[];
    const uint32_t sb = smem_to_u32(sm);

    const int tid  = threadIdx.x;
    const int lane = tid & 31;
    const int wid  = tid >> 5;
    const int wm   = wid >> 1;
    const int wn   = wid & 1;
    const int row0 = blockIdx.x * 128;
    const int col0 = blockIdx.y * 64;

    const int arow  = tid >> 1;
    const int agrow = row0 + arow;
    const uint32_t asz = (agrow < g.M) ? 16u : 0u;
    const int arx = arow & 7;

    float acc[2][4][4];
#pragma unroll
    for (int i = 0; i < 2; i++)
#pragma unroll
        for (int j = 0; j < 4; j++)
#pragma unroll
            for (int q = 0; q < 4; q++) acc[i][j][q] = 0.0f;

#define PREFETCH(kc, st) do {                                                 \
        const uint32_t base = sb + (st) * STAGE_BYTES;                        \
        const bool kh = (kc) >= g.ksplit;                                     \
        const bf16* ah = kh ? g.a1h : g.a0h;                                  \
        const bf16* al = kh ? g.a1l : g.a0l;                                  \
        const int rl = kh ? g.rl1 : g.rl0;                                    \
        const size_t eo = (size_t)agrow * rl +                                \
                          (size_t)((kh ? (kc) - g.ksplit : (kc)) * 64) +      \
                          ((tid & 1) << 5);                                   \
        _Pragma("unroll")                                                     \
        for (int i2 = 0; i2 < 4; i2++) {                                      \
            const int chunk = ((tid & 1) << 2) + i2;                          \
            const uint32_t off = arow * 128 + ((chunk ^ arx) << 4);           \
            CP16(base + off,         ah + eo + i2 * 8, asz);                  \
            CP16(base + 16384 + off, al + eo + i2 * 8, asz);                  \
        }                                                                     \
        _Pragma("unroll")                                                     \
        for (int j2 = 0; j2 < 2; j2++) {                                      \
            const int task = tid * 2 + j2;                                    \
            const int wrow = task >> 3, wch = task & 7;                       \
            const size_t we = (size_t)(col0 + wrow) * g.w_rl +                \
                              (size_t)(kc) * 64 + wch * 8;                    \
            const uint32_t off = wrow * 128 + ((wch ^ (wrow & 7)) << 4);      \
            CP16(base + 32768 + off, g.wh + we, 16u);                         \
            CP16(base + 40960 + off, g.wl + we, 16u);                         \
        }                                                                     \
        CP_COMMIT();                                                          \
    } while (0)

    PREFETCH(0, 0);
    if (g.nchunks > 1) PREFETCH(1, 1);

    for (int c = 0; c < g.nchunks; c++) {
        if (c + 1 < g.nchunks) CP_WAIT1(); else CP_WAIT0();
        __syncthreads();
        const uint32_t base = sb + (c & 1) * STAGE_BYTES;

#pragma unroll
        for (int kk = 0; kk < 4; kk++) {
            uint32_t ah[2][4], al[2][4], bh[2][4], bl[2][4];
#pragma unroll
            for (int rb = 0; rb < 2; rb++) {
                const int row = wm * 32 + rb * 16 + (lane & 15);
                const int ch  = 2 * kk + (lane >> 4);
                const uint32_t ad = base + row * 128 +
                                    ((ch ^ (row & 7)) << 4);
                LDSM4(ah[rb], ad);
                LDSM4(al[rb], ad + 16384);
            }
#pragma unroll
            for (int q = 0; q < 2; q++) {
                const int sel  = lane >> 3;
                const int wrow = wn * 32 + q * 16 + ((sel >> 1) << 3) + (lane & 7);
                const int ch   = 2 * kk + (sel & 1);
                const uint32_t wd = base + 32768 + wrow * 128 +
                                    ((ch ^ (wrow & 7)) << 4);
                LDSM4(bh[q], wd);
                LDSM4(bl[q], wd + 8192);
            }
#pragma unroll
            for (int rb = 0; rb < 2; rb++) {
#pragma unroll
                for (int nb = 0; nb < 4; nb++) {
                    const uint32_t b0h = bh[nb >> 1][(nb & 1) * 2];
                    const uint32_t b1h = bh[nb >> 1][(nb & 1) * 2 + 1];
                    const uint32_t b0l = bl[nb >> 1][(nb & 1) * 2];
                    const uint32_t b1l = bl[nb >> 1][(nb & 1) * 2 + 1];
                    MMA_BF16(acc[rb][nb], ah[rb], b0h, b1h);
                    MMA_BF16(acc[rb][nb], ah[rb], b0l, b1l);
                    MMA_BF16(acc[rb][nb], al[rb], b0h, b1h);
                }
            }
        }
        __syncthreads();
        if (c + 2 < g.nchunks) PREFETCH(c + 2, c & 1);
    }

    // ---- epilogue ----
    const int gr = lane >> 2;
    const int t4 = lane & 3;

    if (BIAS) {
#pragma unroll
        for (int rb = 0; rb < 2; rb++) {
            const int r1 = row0 + wm * 32 + rb * 16 + gr;
            const int r2 = r1 + 8;
#pragma unroll
            for (int nb = 0; nb < 4; nb++) {
                const int col = col0 + wn * 32 + nb * 8 + t4 * 2;
                const float* ac = acc[rb][nb];
                const float bb0 = g.bias[col], bb1 = g.bias[col + 1];
                if (r1 < g.M) {
                    float v0 = ac[0] + bb0, v1 = ac[1] + bb1;
                    v0 = (v0 > 0.f) ? v0 : LEAKY * v0;
                    v1 = (v1 > 0.f) ? v1 : LEAKY * v1;
                    uint32_t h, l;
                    split2(v0, v1, h, l);
                    *(uint32_t*)(g.oh + (size_t)r1 * g.orl + col) = h;
                    *(uint32_t*)(g.ol + (size_t)r1 * g.orl + col) = l;
                }
                if (r2 < g.M) {
                    float v0 = ac[2] + bb0, v1 = ac[3] + bb1;
                    v0 = (v0 > 0.f) ? v0 : LEAKY * v0;
                    v1 = (v1 > 0.f) ? v1 : LEAKY * v1;
                    uint32_t h, l;
                    split2(v0, v1, h, l);
                    *(uint32_t*)(g.oh + (size_t)r2 * g.orl + col) = h;
                    *(uint32_t*)(g.ol + (size_t)r2 * g.orl + col) = l;
                }
            }
        }
    } else {
        float* outp;
        int ocol0, orl;
        if (col0 < g.csplit) { outp = g.o0; ocol0 = col0; orl = g.orl0; }
        else { outp = g.o1; ocol0 = col0 - g.csplit; orl = g.orl1; }
#pragma unroll
        for (int rb = 0; rb < 2; rb++) {
            const int r1 = row0 + wm * 32 + rb * 16 + gr;
            const int r2 = r1 + 8;
#pragma unroll
            for (int nb = 0; nb < 4; nb++) {
                const int coff = wn * 32 + nb * 8 + t4 * 2;
                const float* ac = acc[rb][nb];
                if (r1 < g.M)
                    *(float2*)(outp + (size_t)r1 * orl + ocol0 + coff) =
                        make_float2(ac[0], ac[1]);
                if (r2 < g.M)
                    *(float2*)(outp + (size_t)r2 * orl + ocol0 + coff) =
                        make_float2(ac[2], ac[3]);
            }
        }
    }
#undef PREFETCH
}

// --------------------------- host side --------------------------------------
extern "C" void kernel_launch(void* const* d_in, const int* in_sizes, int n_in,
                              void* d_out, int out_size) {
    const float* x    = (const float*)d_in[0];
    const void*  eidx = d_in[1];
    WPtrs w;
    w.rel0  = (const float*)d_in[2];
    w.root0 = (const float*)d_in[3];
    const float* b0 = (const float*)d_in[4];
    w.rel1  = (const float*)d_in[5];
    w.root1 = (const float*)d_in[6];
    const float* b1 = (const float*)d_in[7];
    w.rel2  = (const float*)d_in[8];
    w.root2 = (const float*)d_in[9];
    const float* b2 = (const float*)d_in[10];
    w.rel3  = (const float*)d_in[11];
    w.root3 = (const float*)d_in[12];
    const float* b3 = (const float*)d_in[13];

    const int N = in_sizes[0] / 128;
    const int E = in_sizes[1] / 2;
    float* out = (float*)d_out;

    float *t, *s, *embS;
    bf16 *bufh, *bufl, *aggh, *aggl, *xh, *xl, *embh, *embl, *wh, *wl;
    cudaGetSymbolAddress((void**)&t,    g_t);
    cudaGetSymbolAddress((void**)&s,    g_s);
    cudaGetSymbolAddress((void**)&embS, g_emb);
    cudaGetSymbolAddress((void**)&bufh, g_bufh);
    cudaGetSymbolAddress((void**)&bufl, g_bufl);
    cudaGetSymbolAddress((void**)&aggh, g_aggh);
    cudaGetSymbolAddress((void**)&aggl, g_aggl);
    cudaGetSymbolAddress((void**)&xh,   g_xh);
    cudaGetSymbolAddress((void**)&xl,   g_xl);
    cudaGetSymbolAddress((void**)&embh, g_embh);
    cudaGetSymbolAddress((void**)&embl, g_embl);
    cudaGetSymbolAddress((void**)&wh,   g_wh);
    cudaGetSymbolAddress((void**)&wl,   g_wl);

    float* emb = ((long long)out_size >= (long long)N * 192)
                     ? out + (size_t)N * 128 : embS;

    static bool attr_done = false;
    if (!attr_done) {
        cudaFuncSetAttribute(mma_gemm<true>,
            cudaFuncAttributeMaxDynamicSharedMemorySize, 2 * STAGE_BYTES);
        cudaFuncSetAttribute(mma_gemm<false>,
            cudaFuncAttributeMaxDynamicSharedMemorySize, 2 * STAGE_BYTES);
        attr_done = true;
    }

    const int MT = (N + 127) / 128;
    const int AGGB = (N * 32 + 255) / 256;

    // ---- CSR chain: 4 launches ----
    zero_cnt<<<(2 * N + 255) / 256, 256>>>(2 * N);                  // 1
    {
        int half = (E + 1) / 2;
        econv_hist<<<(half + 255) / 256, 256>>>(
            (const unsigned int*)eidx, E);                          // 2
    }
    scan_full<<<1, 1024>>>(N);                                      // 3
    {
        int half = (E + 1) / 2;
        fill_kernel<<<(half + 255) / 256, 256>>>(E, N);             // 4
    }

    // ---- Layer 0 aggregation ----
    agg128_kernel<0><<<AGGB, 256>>>(x, nullptr, aggh, aggl,
                                    nullptr, nullptr, N);           // 5

    // ---- setup: weight + x bf16 splits ----
    {
        long long xn8 = (long long)N * 16;
        long long tot = WTASKS + xn8;
        setup_kernel<<<(int)((tot + 255) / 256), 256>>>(w, wh, wl,
                                                        x, xh, xl, xn8);
    }

    // ---- Layer 0 GEMM: buf = leaky([agg||x] @ Wcat0^T + b0) ----
    {
        GArgs a = {};
        a.a0h = aggh; a.a0l = aggl; a.a1h = xh; a.a1l = xl;
        a.rl0 = 128; a.rl1 = 128; a.ksplit = 2; a.nchunks = 4;
        a.wh = wh; a.wl = wl; a.w_rl = 256;
        a.bias = b0; a.oh = bufh; a.ol = bufl; a.orl = 256; a.M = N;
        mma_gemm<true><<<dim3(MT, 4), 256, 2 * STAGE_BYTES>>>(a);
    }

    // ---- Layer 1: [t|s] = buf @ [Wrel1;Wroot1]^T; emb = leaky(seg(t)+s+b1) --
    {
        GArgs a = {};
        a.a0h = bufh; a.a0l = bufl; a.a1h = bufh; a.a1l = bufl;
        a.rl0 = 256; a.rl1 = 256; a.ksplit = 4; a.nchunks = 4;
        a.wh = wh + 65536; a.wl = wl + 65536; a.w_rl = 256;
        a.o0 = t; a.o1 = s; a.csplit = 64; a.orl0 = 64; a.orl1 = 64; a.M = N;
        mma_gemm<false><<<dim3(MT, 2), 256, 2 * STAGE_BYTES>>>(a);
    }
    agg64_kernel<2><<<AGGB, 256>>>(t, emb, embh, embl, s, b1, N);

    // ---- Layer 2: agg = segsum(emb) (split); buf = leaky([agg||emb]@W2^T+b2)
    agg64_kernel<0><<<AGGB, 256>>>(emb, nullptr, aggh, aggl,
                                   nullptr, nullptr, N);
    {
        GArgs a = {};
        a.a0h = aggh; a.a0l = aggl; a.a1h = embh; a.a1l = embl;
        a.rl0 = 64; a.rl1 = 64; a.ksplit = 1; a.nchunks = 2;
        a.wh = wh + 98304; a.wl = wl + 98304; a.w_rl = 128;
        a.bias = b2; a.oh = bufh; a.ol = bufl; a.orl = 256; a.M = N;
        mma_gemm<true><<<dim3(MT, 4), 256, 2 * STAGE_BYTES>>>(a);
    }

    // ---- Layer 3: [t|s] = buf @ [Wrel3;Wroot3]^T; out = leaky(seg(t)+s+b3) --
    {
        GArgs a = {};
        a.a0h = bufh; a.a0l = bufl; a.a1h = bufh; a.a1l = bufl;
        a.rl0 = 256; a.rl1 = 256; a.ksplit = 4; a.nchunks = 4;
        a.wh = wh + 131072; a.wl = wl + 131072; a.w_rl = 256;
        a.o0 = t; a.o1 = s; a.csplit = 128; a.orl0 = 128; a.orl1 = 128; a.M = N;
        mma_gemm<false><<<dim3(MT, 4), 256, 2 * STAGE_BYTES>>>(a);
    }
    agg128_kernel<1><<<AGGB, 256>>>(t, out, nullptr, nullptr, s, b3, N);
}

// round 14
// speedup vs baseline: 1.1128x; 1.1128x over previous
#include <cuda_runtime.h>
#include <cuda_bf16.h>
#include <cstdint>

// ---------------------------------------------------------------------------
// SDNE graph autoencoder: 4x GraphConv (PyG) + leaky_relu(0.01).
//   layer: out = segsum(h[src]->dst) @ Wrel^T + b + h @ Wroot^T
// Linearity: aggregate in min(d_in, d_out) dim.
// Aggregation: CSR (zero | decode+detect+hist | shfl scan | parallel scan_add
//   | fill) + warp-per-node gather; epilogues emit bf16 hi/lo splits.
// GEMM: mma.sync m16n8k16 bf16 hi/lo split (D += Ah*Bh + Ah*Bl + Al*Bh),
//   128x64 CTA tile, 2-stage cp.async, one launch per layer.
// ---------------------------------------------------------------------------

#define NMAX  50000
#define EMAX  1000000
#define LEAKY 0.01f
typedef __nv_bfloat16 bf16;

// ------------------------------- scratch -----------------------------------
__device__ __align__(16) float g_t   [(size_t)NMAX * 128];
__device__ __align__(16) float g_s   [(size_t)NMAX * 128];
__device__ __align__(16) float g_emb [(size_t)NMAX * 64];
__device__ __align__(16) bf16  g_bufh[(size_t)NMAX * 256];
__device__ __align__(16) bf16  g_bufl[(size_t)NMAX * 256];
__device__ __align__(16) bf16  g_aggh[(size_t)NMAX * 128];
__device__ __align__(16) bf16  g_aggl[(size_t)NMAX * 128];
__device__ __align__(16) bf16  g_xh  [(size_t)NMAX * 128];
__device__ __align__(16) bf16  g_xl  [(size_t)NMAX * 128];
__device__ __align__(16) bf16  g_embh[(size_t)NMAX * 64];
__device__ __align__(16) bf16  g_embl[(size_t)NMAX * 64];
__device__ __align__(16) bf16  g_wh  [262144];
__device__ __align__(16) bf16  g_wl  [262144];
__device__ int g_rowptr[NMAX + 1];
__device__ int g_cnt   [2 * NMAX];
__device__ __align__(16) int g_csr   [EMAX];
__device__ __align__(16) int g_src   [EMAX];
__device__ __align__(16) int g_dst   [EMAX];
__device__ int g_tmp   [NMAX];
__device__ int g_bsum  [64];

// --------------------------- helpers ----------------------------------------
__device__ __forceinline__ uint32_t smem_to_u32(const void* p) {
    uint32_t a;
    asm("{ .reg .u64 t; cvta.to.shared.u64 t, %1; cvt.u32.u64 %0, t; }"
        : "=r"(a) : "l"(p));
    return a;
}

#define LDSM4(r, addr) \
    asm volatile("ldmatrix.sync.aligned.m8n8.x4.shared.b16 {%0,%1,%2,%3}, [%4];" \
        : "=r"((r)[0]), "=r"((r)[1]), "=r"((r)[2]), "=r"((r)[3]) : "r"(addr))

#define MMA_BF16(c, a, b0r, b1r) \
    asm volatile("mma.sync.aligned.m16n8k16.row.col.f32.bf16.bf16.f32 " \
        "{%0,%1,%2,%3}, {%4,%5,%6,%7}, {%8,%9}, {%0,%1,%2,%3};" \
        : "+f"((c)[0]), "+f"((c)[1]), "+f"((c)[2]), "+f"((c)[3]) \
        : "r"((a)[0]), "r"((a)[1]), "r"((a)[2]), "r"((a)[3]), \
          "r"(b0r), "r"(b1r))

#define CP16(dst, src, sz) \
    asm volatile("cp.async.cg.shared.global [%0], [%1], 16, %2;" \
        :: "r"(dst), "l"(src), "r"(sz) : "memory")
#define CP_COMMIT() asm volatile("cp.async.commit_group;" ::: "memory")
#define CP_WAIT0()  asm volatile("cp.async.wait_group 0;" ::: "memory")
#define CP_WAIT1()  asm volatile("cp.async.wait_group 1;" ::: "memory")

__device__ __forceinline__ void split2(float v0, float v1,
                                       uint32_t& h, uint32_t& l) {
    bf16 h0 = __float2bfloat16(v0), h1 = __float2bfloat16(v1);
    float r0 = v0 - __bfloat162float(h0);
    float r1 = v1 - __bfloat162float(h1);
    __nv_bfloat162 hh = __halves2bfloat162(h0, h1);
    __nv_bfloat162 ll = __halves2bfloat162(__float2bfloat16(r0),
                                           __float2bfloat16(r1));
    h = *(uint32_t*)&hh;
    l = *(uint32_t*)&ll;
}
__device__ __forceinline__ void split8(float4 a, float4 b, uint4& h, uint4& l) {
    split2(a.x, a.y, h.x, l.x);
    split2(a.z, a.w, h.y, l.y);
    split2(b.x, b.y, h.z, l.z);
    split2(b.z, b.w, h.w, l.w);
}

// --------------------------- CSR build --------------------------------------
// counters zeroed in a SEPARATE kernel: the zero-vs-atomic ordering across
// blocks is a real dependency (fusing it into the histogram kernel is a race).
__global__ void zero_cnt(int n2) {
    int i = blockIdx.x * blockDim.x + threadIdx.x;
    if (i < n2) g_cnt[i] = 0;
}

// decode 2 edges/thread to int32 + histogram of dst, with per-block
// int64-vs-int32 detection (OR of first 1024 odd words).
__global__ void econv_hist(const unsigned int* __restrict__ ew, int E) {
    unsigned int any = 0;
    int lim = (E < 1024) ? E : 1024;
    for (int k = threadIdx.x; k < lim; k += blockDim.x)
        any |= ew[2 * k + 1];
    unsigned int anynz = __syncthreads_or(any != 0u);
    const int is64 = anynz ? 0 : 1;

    int i = blockIdx.x * blockDim.x + threadIdx.x;
    int e = 2 * i;
    if (e >= E) return;
    int s0, s1, d0, d1;
    bool two = (e + 1 < E);
    if (is64) {
        const long long* p = (const long long*)ew;
        if (two) {
            longlong2 sv = *(const longlong2*)(p + e);
            longlong2 dv = *(const longlong2*)(p + E + e);
            s0 = (int)sv.x; s1 = (int)sv.y;
            d0 = (int)dv.x; d1 = (int)dv.y;
        } else {
            s0 = (int)p[e]; d0 = (int)p[E + e];
            s1 = 0; d1 = 0;
        }
    } else {
        const int* p = (const int*)ew;
        if (two) {
            int2 sv = *(const int2*)(p + e);
            int2 dv = *(const int2*)(p + E + e);
            s0 = sv.x; s1 = sv.y; d0 = dv.x; d1 = dv.y;
        } else {
            s0 = p[e]; d0 = p[E + e];
            s1 = 0; d1 = 0;
        }
    }
    if (two) {
        *(int2*)(g_src + e) = make_int2(s0, s1);
        *(int2*)(g_dst + e) = make_int2(d0, d1);
        atomicAdd(&g_cnt[d0], 1);
        atomicAdd(&g_cnt[d1], 1);
    } else {
        g_src[e] = s0; g_dst[e] = d0;
        atomicAdd(&g_cnt[d0], 1);
    }
}

// shuffle-based block-inclusive scan (2 barriers), 1024 elems per block
__global__ void scan_block(int n) {
    __shared__ int warp_sums[32];
    int i = blockIdx.x * 1024 + threadIdx.x;
    int v = (i < n) ? g_cnt[i] : 0;
    int lane = threadIdx.x & 31;
    int wid  = threadIdx.x >> 5;
    int s = v;
#pragma unroll
    for (int o = 1; o < 32; o <<= 1) {
        int t = __shfl_up_sync(0xFFFFFFFFu, s, o);
        if (lane >= o) s += t;
    }
    if (lane == 31) warp_sums[wid] = s;
    __syncthreads();
    if (wid == 0) {
        int ws = warp_sums[lane];
#pragma unroll
        for (int o = 1; o < 32; o <<= 1) {
            int t = __shfl_up_sync(0xFFFFFFFFu, ws, o);
            if (lane >= o) ws += t;
        }
        warp_sums[lane] = ws;
    }
    __syncthreads();
    int incl = (wid ? warp_sums[wid - 1] : 0) + s;
    if (i < n) g_tmp[i] = incl;
    if (threadIdx.x == 1023) g_bsum[blockIdx.x] = incl;
}

// per-block parallel top-level scan (64 elems, smem Hillis-Steele), then add
__global__ void scan_add(int n, int nb) {
    __shared__ int soff[64];
    if (threadIdx.x < 64)
        soff[threadIdx.x] = (threadIdx.x < nb) ? g_bsum[threadIdx.x] : 0;
    __syncthreads();
#pragma unroll
    for (int o = 1; o < 64; o <<= 1) {
        int t = (threadIdx.x < 64 && threadIdx.x >= o) ? soff[threadIdx.x - o] : 0;
        __syncthreads();
        if (threadIdx.x < 64) soff[threadIdx.x] += t;
        __syncthreads();
    }
    // soff is now INCLUSIVE scan; block b needs exclusive offset soff[b-1]
    int i = blockIdx.x * blockDim.x + threadIdx.x;
    if (i < n) {
        int b = i >> 10;
        int off = b ? soff[b - 1] : 0;
        g_rowptr[i + 1] = g_tmp[i] + off;
    }
    if (i == 0) g_rowptr[0] = 0;
}

// 2 edges/thread CSR fill
__global__ void fill_kernel(int E, int n) {
    int i = blockIdx.x * blockDim.x + threadIdx.x;
    int e = 2 * i;
    if (e >= E) return;
    if (e + 1 < E) {
        int2 d  = *(const int2*)(g_dst + e);
        int2 sv = *(const int2*)(g_src + e);
        int p0 = atomicAdd(&g_cnt[n + d.x], 1);
        g_csr[g_rowptr[d.x] + p0] = sv.x;
        int p1 = atomicAdd(&g_cnt[n + d.y], 1);
        g_csr[g_rowptr[d.y] + p1] = sv.y;
    } else {
        int d = g_dst[e], sv = g_src[e];
        int p = atomicAdd(&g_cnt[n + d], 1);
        g_csr[g_rowptr[d] + p] = sv;
    }
}

// ------------------------ warp-per-node aggregation --------------------------
// MODE: 0 = write bf16 hi/lo split only (GEMM A input)
//       1 = out fp32 = leaky(sum + s + b)                       (final layer)
//       2 = MODE1 + also write bf16 hi/lo split                 (emb layer)
template <int MODE>
__global__ void agg128_kernel(const float* __restrict__ feat,
                              float* __restrict__ outp,
                              bf16* __restrict__ oh, bf16* __restrict__ ol,
                              const float* __restrict__ svec,
                              const float* __restrict__ bias, int n) {
    int node = (int)((blockIdx.x * (long long)blockDim.x + threadIdx.x) >> 5);
    int lane = threadIdx.x & 31;
    if (node >= n) return;
    int beg = g_rowptr[node], end = g_rowptr[node + 1];
    const int c = lane * 4;
    float4 acc = make_float4(0.f, 0.f, 0.f, 0.f);
    int e = beg;
    for (; e + 1 < end; e += 2) {
        int s0 = g_csr[e], s1 = g_csr[e + 1];
        float4 v0 = *(const float4*)(feat + (size_t)s0 * 128 + c);
        float4 v1 = *(const float4*)(feat + (size_t)s1 * 128 + c);
        acc.x += v0.x; acc.y += v0.y; acc.z += v0.z; acc.w += v0.w;
        acc.x += v1.x; acc.y += v1.y; acc.z += v1.z; acc.w += v1.w;
    }
    if (e < end) {
        float4 v0 = *(const float4*)(feat + (size_t)g_csr[e] * 128 + c);
        acc.x += v0.x; acc.y += v0.y; acc.z += v0.z; acc.w += v0.w;
    }
    float4 r = acc;
    if (MODE >= 1) {
        float4 sv = *(const float4*)(svec + (size_t)node * 128 + c);
        float4 bv = *(const float4*)(bias + c);
        r.x = acc.x + sv.x + bv.x; r.y = acc.y + sv.y + bv.y;
        r.z = acc.z + sv.z + bv.z; r.w = acc.w + sv.w + bv.w;
        r.x = (r.x > 0.f) ? r.x : LEAKY * r.x;
        r.y = (r.y > 0.f) ? r.y : LEAKY * r.y;
        r.z = (r.z > 0.f) ? r.z : LEAKY * r.z;
        r.w = (r.w > 0.f) ? r.w : LEAKY * r.w;
        *(float4*)(outp + (size_t)node * 128 + c) = r;
    }
    if (MODE != 1) {
        uint32_t h0, l0, h1, l1;
        split2(r.x, r.y, h0, l0);
        split2(r.z, r.w, h1, l1);
        *(uint2*)(oh + (size_t)node * 128 + c) = make_uint2(h0, h1);
        *(uint2*)(ol + (size_t)node * 128 + c) = make_uint2(l0, l1);
    }
}

template <int MODE>
__global__ void agg64_kernel(const float* __restrict__ feat,
                             float* __restrict__ outp,
                             bf16* __restrict__ oh, bf16* __restrict__ ol,
                             const float* __restrict__ svec,
                             const float* __restrict__ bias, int n) {
    int node = (int)((blockIdx.x * (long long)blockDim.x + threadIdx.x) >> 5);
    int lane = threadIdx.x & 31;
    if (node >= n) return;
    int beg = g_rowptr[node], end = g_rowptr[node + 1];
    const int c = lane * 2;
    float2 a0 = make_float2(0.f, 0.f), a1 = a0;
    int e = beg;
    for (; e + 1 < end; e += 2) {
        int s0 = g_csr[e], s1 = g_csr[e + 1];
        float2 v0 = *(const float2*)(feat + (size_t)s0 * 64 + c);
        float2 v1 = *(const float2*)(feat + (size_t)s1 * 64 + c);
        a0.x += v0.x; a0.y += v0.y;
        a1.x += v1.x; a1.y += v1.y;
    }
    if (e < end) {
        float2 v0 = *(const float2*)(feat + (size_t)g_csr[e] * 64 + c);
        a0.x += v0.x; a0.y += v0.y;
    }
    float2 r = make_float2(a0.x + a1.x, a0.y + a1.y);
    if (MODE >= 1) {
        float2 sv = *(const float2*)(svec + (size_t)node * 64 + c);
        float2 bv = *(const float2*)(bias + c);
        r.x += sv.x + bv.x;
        r.y += sv.y + bv.y;
        r.x = (r.x > 0.f) ? r.x : LEAKY * r.x;
        r.y = (r.y > 0.f) ? r.y : LEAKY * r.y;
        *(float2*)(outp + (size_t)node * 64 + c) = r;
    }
    if (MODE != 1) {
        uint32_t h0, l0;
        split2(r.x, r.y, h0, l0);
        *(uint32_t*)(oh + (size_t)node * 64 + c) = h0;
        *(uint32_t*)(ol + (size_t)node * 64 + c) = l0;
    }
}

// --------------------- fused setup: weight split + x split -------------------
//  weight layout in g_wh/g_wl (bf16):
//  [0,      65536): L0 cat:   256 x 256  (cols 0-127 Wrel0, 128-255 Wroot0)
//  [65536,  98304): L1 stack: 128 x 256  (rows 0-63 Wrel1, 64-127 Wroot1)
//  [98304, 131072): L2 cat:   256 x 128  (cols 0-63 Wrel2, 64-127 Wroot2)
//  [131072,196608): L3 stack: 256 x 256  (rows 0-127 Wrel3, 128-255 Wroot3)
struct WPtrs {
    const float *rel0, *root0, *rel1, *root1, *rel2, *root2, *rel3, *root3;
};
#define WTASKS (196608 / 8)

__global__ void setup_kernel(WPtrs w, bf16* __restrict__ wh,
                             bf16* __restrict__ wl,
                             const float* __restrict__ x,
                             bf16* __restrict__ xh, bf16* __restrict__ xl,
                             long long xn8) {
    long long i = (long long)blockIdx.x * blockDim.x + threadIdx.x;
    if (i < WTASKS) {
        int base = (int)i * 8;
        const float* src;
        if (base < 65536) {
            int row = base >> 8, col = base & 255;
            src = (col < 128) ? w.rel0 + row * 128 + col
                              : w.root0 + row * 128 + (col - 128);
        } else if (base < 98304) {
            int j = base - 65536, row = j >> 8, col = j & 255;
            src = (row < 64) ? w.rel1 + row * 256 + col
                             : w.root1 + (row - 64) * 256 + col;
        } else if (base < 131072) {
            int j = base - 98304, row = j >> 7, col = j & 127;
            src = (col < 64) ? w.rel2 + row * 64 + col
                             : w.root2 + row * 64 + (col - 64);
        } else {
            int j = base - 131072, row = j >> 8, col = j & 255;
            src = (row < 128) ? w.rel3 + row * 256 + col
                              : w.root3 + (row - 128) * 256 + col;
        }
        float4 v0 = *(const float4*)src;
        float4 v1 = *(const float4*)(src + 4);
        uint4 h, l;
        split8(v0, v1, h, l);
        ((uint4*)wh)[i] = h;
        ((uint4*)wl)[i] = l;
        return;
    }
    long long j = i - WTASKS;
    if (j >= xn8) return;
    const float4* p = (const float4*)x + j * 2;
    uint4 h, l;
    split8(p[0], p[1], h, l);
    ((uint4*)xh)[j] = h;
    ((uint4*)xl)[j] = l;
}

// --------------------------- MMA GEMM ---------------------------------------
// C tile = A[M, K](bf16 pre-split) @ W[*, K](bf16 pre-split)^T
// Block: 256 thr (8 warps 4Mx2N), tile 128M x 64N, BK=64, chunk-xor swizzle,
// 2-stage cp.async pipeline (stage 48KB: A hi 16K, A lo 16K, W hi 8K, W lo 8K).
struct GArgs {
    const bf16 *a0h, *a0l, *a1h, *a1l;   // A sources (chunks >= ksplit -> a1)
    int rl0, rl1;                        // A row lengths (bf16 elems)
    int ksplit, nchunks;                 // 64-wide K chunks
    const bf16 *wh, *wl;                 // pre-split W base
    int w_rl;                            // W row length = K total
    const float* bias;                   // BIAS mode
    bf16 *oh, *ol; int orl;              // BIAS out (bf16 split)
    float *o0, *o1;                      // !BIAS out, split at column csplit
    int csplit, orl0, orl1;
    int M;
};

#define STAGE_BYTES 49152

template <bool BIAS>
__global__ void __launch_bounds__(256) mma_gemm(GArgs g) {
    extern __shared__ __align__(16) unsigned char sm[];
    const uint32_t sb = smem_to_u32(sm);

    const int tid  = threadIdx.x;
    const int lane = tid & 31;
    const int wid  = tid >> 5;
    const int wm   = wid >> 1;
    const int wn   = wid & 1;
    const int row0 = blockIdx.x * 128;
    const int col0 = blockIdx.y * 64;

    const int arow  = tid >> 1;
    const int agrow = row0 + arow;
    const uint32_t asz = (agrow < g.M) ? 16u : 0u;
    const int arx = arow & 7;

    float acc[2][4][4];
#pragma unroll
    for (int i = 0; i < 2; i++)
#pragma unroll
        for (int j = 0; j < 4; j++)
#pragma unroll
            for (int q = 0; q < 4; q++) acc[i][j][q] = 0.0f;

#define PREFETCH(kc, st) do {                                                 \
        const uint32_t base = sb + (st) * STAGE_BYTES;                        \
        const bool kh = (kc) >= g.ksplit;                                     \
        const bf16* ah = kh ? g.a1h : g.a0h;                                  \
        const bf16* al = kh ? g.a1l : g.a0l;                                  \
        const int rl = kh ? g.rl1 : g.rl0;                                    \
        const size_t eo = (size_t)agrow * rl +                                \
                          (size_t)((kh ? (kc) - g.ksplit : (kc)) * 64) +      \
                          ((tid & 1) << 5);                                   \
        _Pragma("unroll")                                                     \
        for (int i2 = 0; i2 < 4; i2++) {                                      \
            const int chunk = ((tid & 1) << 2) + i2;                          \
            const uint32_t off = arow * 128 + ((chunk ^ arx) << 4);           \
            CP16(base + off,         ah + eo + i2 * 8, asz);                  \
            CP16(base + 16384 + off, al + eo + i2 * 8, asz);                  \
        }                                                                     \
        _Pragma("unroll")                                                     \
        for (int j2 = 0; j2 < 2; j2++) {                                      \
            const int task = tid * 2 + j2;                                    \
            const int wrow = task >> 3, wch = task & 7;                       \
            const size_t we = (size_t)(col0 + wrow) * g.w_rl +                \
                              (size_t)(kc) * 64 + wch * 8;                    \
            const uint32_t off = wrow * 128 + ((wch ^ (wrow & 7)) << 4);      \
            CP16(base + 32768 + off, g.wh + we, 16u);                         \
            CP16(base + 40960 + off, g.wl + we, 16u);                         \
        }                                                                     \
        CP_COMMIT();                                                          \
    } while (0)

    PREFETCH(0, 0);
    if (g.nchunks > 1) PREFETCH(1, 1);

    for (int c = 0; c < g.nchunks; c++) {
        if (c + 1 < g.nchunks) CP_WAIT1(); else CP_WAIT0();
        __syncthreads();
        const uint32_t base = sb + (c & 1) * STAGE_BYTES;

#pragma unroll
        for (int kk = 0; kk < 4; kk++) {
            uint32_t ah[2][4], al[2][4], bh[2][4], bl[2][4];
#pragma unroll
            for (int rb = 0; rb < 2; rb++) {
                const int row = wm * 32 + rb * 16 + (lane & 15);
                const int ch  = 2 * kk + (lane >> 4);
                const uint32_t ad = base + row * 128 +
                                    ((ch ^ (row & 7)) << 4);
                LDSM4(ah[rb], ad);
                LDSM4(al[rb], ad + 16384);
            }
#pragma unroll
            for (int q = 0; q < 2; q++) {
                const int sel  = lane >> 3;
                const int wrow = wn * 32 + q * 16 + ((sel >> 1) << 3) + (lane & 7);
                const int ch   = 2 * kk + (sel & 1);
                const uint32_t wd = base + 32768 + wrow * 128 +
                                    ((ch ^ (wrow & 7)) << 4);
                LDSM4(bh[q], wd);
                LDSM4(bl[q], wd + 8192);
            }
#pragma unroll
            for (int rb = 0; rb < 2; rb++) {
#pragma unroll
                for (int nb = 0; nb < 4; nb++) {
                    const uint32_t b0h = bh[nb >> 1][(nb & 1) * 2];
                    const uint32_t b1h = bh[nb >> 1][(nb & 1) * 2 + 1];
                    const uint32_t b0l = bl[nb >> 1][(nb & 1) * 2];
                    const uint32_t b1l = bl[nb >> 1][(nb & 1) * 2 + 1];
                    MMA_BF16(acc[rb][nb], ah[rb], b0h, b1h);
                    MMA_BF16(acc[rb][nb], ah[rb], b0l, b1l);
                    MMA_BF16(acc[rb][nb], al[rb], b0h, b1h);
                }
            }
        }
        __syncthreads();
        if (c + 2 < g.nchunks) PREFETCH(c + 2, c & 1);
    }

    // ---- epilogue ----
    const int gr = lane >> 2;
    const int t4 = lane & 3;

    if (BIAS) {
#pragma unroll
        for (int rb = 0; rb < 2; rb++) {
            const int r1 = row0 + wm * 32 + rb * 16 + gr;
            const int r2 = r1 + 8;
#pragma unroll
            for (int nb = 0; nb < 4; nb++) {
                const int col = col0 + wn * 32 + nb * 8 + t4 * 2;
                const float* ac = acc[rb][nb];
                const float bb0 = g.bias[col], bb1 = g.bias[col + 1];
                if (r1 < g.M) {
                    float v0 = ac[0] + bb0, v1 = ac[1] + bb1;
                    v0 = (v0 > 0.f) ? v0 : LEAKY * v0;
                    v1 = (v1 > 0.f) ? v1 : LEAKY * v1;
                    uint32_t h, l;
                    split2(v0, v1, h, l);
                    *(uint32_t*)(g.oh + (size_t)r1 * g.orl + col) = h;
                    *(uint32_t*)(g.ol + (size_t)r1 * g.orl + col) = l;
                }
                if (r2 < g.M) {
                    float v0 = ac[2] + bb0, v1 = ac[3] + bb1;
                    v0 = (v0 > 0.f) ? v0 : LEAKY * v0;
                    v1 = (v1 > 0.f) ? v1 : LEAKY * v1;
                    uint32_t h, l;
                    split2(v0, v1, h, l);
                    *(uint32_t*)(g.oh + (size_t)r2 * g.orl + col) = h;
                    *(uint32_t*)(g.ol + (size_t)r2 * g.orl + col) = l;
                }
            }
        }
    } else {
        float* outp;
        int ocol0, orl;
        if (col0 < g.csplit) { outp = g.o0; ocol0 = col0; orl = g.orl0; }
        else { outp = g.o1; ocol0 = col0 - g.csplit; orl = g.orl1; }
#pragma unroll
        for (int rb = 0; rb < 2; rb++) {
            const int r1 = row0 + wm * 32 + rb * 16 + gr;
            const int r2 = r1 + 8;
#pragma unroll
            for (int nb = 0; nb < 4; nb++) {
                const int coff = wn * 32 + nb * 8 + t4 * 2;
                const float* ac = acc[rb][nb];
                if (r1 < g.M)
                    *(float2*)(outp + (size_t)r1 * orl + ocol0 + coff) =
                        make_float2(ac[0], ac[1]);
                if (r2 < g.M)
                    *(float2*)(outp + (size_t)r2 * orl + ocol0 + coff) =
                        make_float2(ac[2], ac[3]);
            }
        }
    }
#undef PREFETCH
}

// --------------------------- host side --------------------------------------
extern "C" void kernel_launch(void* const* d_in, const int* in_sizes, int n_in,
                              void* d_out, int out_size) {
    const float* x    = (const float*)d_in[0];
    const void*  eidx = d_in[1];
    WPtrs w;
    w.rel0  = (const float*)d_in[2];
    w.root0 = (const float*)d_in[3];
    const float* b0 = (const float*)d_in[4];
    w.rel1  = (const float*)d_in[5];
    w.root1 = (const float*)d_in[6];
    const float* b1 = (const float*)d_in[7];
    w.rel2  = (const float*)d_in[8];
    w.root2 = (const float*)d_in[9];
    const float* b2 = (const float*)d_in[10];
    w.rel3  = (const float*)d_in[11];
    w.root3 = (const float*)d_in[12];
    const float* b3 = (const float*)d_in[13];

    const int N = in_sizes[0] / 128;
    const int E = in_sizes[1] / 2;
    float* out = (float*)d_out;

    float *t, *s, *embS;
    bf16 *bufh, *bufl, *aggh, *aggl, *xh, *xl, *embh, *embl, *wh, *wl;
    cudaGetSymbolAddress((void**)&t,    g_t);
    cudaGetSymbolAddress((void**)&s,    g_s);
    cudaGetSymbolAddress((void**)&embS, g_emb);
    cudaGetSymbolAddress((void**)&bufh, g_bufh);
    cudaGetSymbolAddress((void**)&bufl, g_bufl);
    cudaGetSymbolAddress((void**)&aggh, g_aggh);
    cudaGetSymbolAddress((void**)&aggl, g_aggl);
    cudaGetSymbolAddress((void**)&xh,   g_xh);
    cudaGetSymbolAddress((void**)&xl,   g_xl);
    cudaGetSymbolAddress((void**)&embh, g_embh);
    cudaGetSymbolAddress((void**)&embl, g_embl);
    cudaGetSymbolAddress((void**)&wh,   g_wh);
    cudaGetSymbolAddress((void**)&wl,   g_wl);

    float* emb = ((long long)out_size >= (long long)N * 192)
                     ? out + (size_t)N * 128 : embS;

    static bool attr_done = false;
    if (!attr_done) {
        cudaFuncSetAttribute(mma_gemm<true>,
            cudaFuncAttributeMaxDynamicSharedMemorySize, 2 * STAGE_BYTES);
        cudaFuncSetAttribute(mma_gemm<false>,
            cudaFuncAttributeMaxDynamicSharedMemorySize, 2 * STAGE_BYTES);
        attr_done = true;
    }

    const int MT = (N + 127) / 128;
    const int AGGB = (N * 32 + 255) / 256;
    const int nb = (N + 1023) / 1024;

    // ---- CSR chain: 5 launches (zero kept separate: correctness) ----
    zero_cnt<<<(2 * N + 255) / 256, 256>>>(2 * N);
    {
        int half = (E + 1) / 2;
        econv_hist<<<(half + 255) / 256, 256>>>((const unsigned int*)eidx, E);
    }
    scan_block<<<nb, 1024>>>(N);
    scan_add<<<(N + 511) / 512, 512>>>(N, nb);
    {
        int half = (E + 1) / 2;
        fill_kernel<<<(half + 255) / 256, 256>>>(E, N);
    }

    // ---- Layer 0 aggregation ----
    agg128_kernel<0><<<AGGB, 256>>>(x, nullptr, aggh, aggl,
                                    nullptr, nullptr, N);

    // ---- setup: weight + x bf16 splits ----
    {
        long long xn8 = (long long)N * 16;
        long long tot = WTASKS + xn8;
        setup_kernel<<<(int)((tot + 255) / 256), 256>>>(w, wh, wl,
                                                        x, xh, xl, xn8);
    }

    // ---- Layer 0 GEMM: buf = leaky([agg||x] @ Wcat0^T + b0) ----
    {
        GArgs a = {};
        a.a0h = aggh; a.a0l = aggl; a.a1h = xh; a.a1l = xl;
        a.rl0 = 128; a.rl1 = 128; a.ksplit = 2; a.nchunks = 4;
        a.wh = wh; a.wl = wl; a.w_rl = 256;
        a.bias = b0; a.oh = bufh; a.ol = bufl; a.orl = 256; a.M = N;
        mma_gemm<true><<<dim3(MT, 4), 256, 2 * STAGE_BYTES>>>(a);
    }

    // ---- Layer 1: [t|s] = buf @ [Wrel1;Wroot1]^T; emb = leaky(seg(t)+s+b1) --
    {
        GArgs a = {};
        a.a0h = bufh; a.a0l = bufl; a.a1h = bufh; a.a1l = bufl;
        a.rl0 = 256; a.rl1 = 256; a.ksplit = 4; a.nchunks = 4;
        a.wh = wh + 65536; a.wl = wl + 65536; a.w_rl = 256;
        a.o0 = t; a.o1 = s; a.csplit = 64; a.orl0 = 64; a.orl1 = 64; a.M = N;
        mma_gemm<false><<<dim3(MT, 2), 256, 2 * STAGE_BYTES>>>(a);
    }
    agg64_kernel<2><<<AGGB, 256>>>(t, emb, embh, embl, s, b1, N);

    // ---- Layer 2: agg = segsum(emb) (split); buf = leaky([agg||emb]@W2^T+b2)
    agg64_kernel<0><<<AGGB, 256>>>(emb, nullptr, aggh, aggl,
                                   nullptr, nullptr, N);
    {
        GArgs a = {};
        a.a0h = aggh; a.a0l = aggl; a.a1h = embh; a.a1l = embl;
        a.rl0 = 64; a.rl1 = 64; a.ksplit = 1; a.nchunks = 2;
        a.wh = wh + 98304; a.wl = wl + 98304; a.w_rl = 128;
        a.bias = b2; a.oh = bufh; a.ol = bufl; a.orl = 256; a.M = N;
        mma_gemm<true><<<dim3(MT, 4), 256, 2 * STAGE_BYTES>>>(a);
    }

    // ---- Layer 3: [t|s] = buf @ [Wrel3;Wroot3]^T; out = leaky(seg(t)+s+b3) --
    {
        GArgs a = {};
        a.a0h = bufh; a.a0l = bufl; a.a1h = bufh; a.a1l = bufl;
        a.rl0 = 256; a.rl1 = 256; a.ksplit = 4; a.nchunks = 4;
        a.wh = wh + 131072; a.wl = wl + 131072; a.w_rl = 256;
        a.o0 = t; a.o1 = s; a.csplit = 128; a.orl0 = 128; a.orl1 = 128; a.M = N;
        mma_gemm<false><<<dim3(MT, 4), 256, 2 * STAGE_BYTES>>>(a);
    }
    agg128_kernel<1><<<AGGB, 256>>>(t, out, nullptr, nullptr, s, b3, N);
}